// round 16
// baseline (speedup 1.0000x reference)
#include <cuda_runtime.h>
#include <cuda_bf16.h>
#include <math.h>
#include <stdint.h>

#define Bb 4
#define Ss 2048
#define Dd 1024
#define Hh 16
#define KD 64
#define Pp 1024
#define Mm (Bb*Ss)          // 8192

// ---------------- scratch (static __device__ per allocation rules) ----------
__device__ __nv_bfloat16 g_a3hi[3*Mm*Dd];     // q|k|v activation splits
__device__ __nv_bfloat16 g_a3lo[3*Mm*Dd];
__device__ __nv_bfloat16 g_w3hi[3*Dd*Pp];     // Wq|Wk|Wv transposed splits [N][K]
__device__ __nv_bfloat16 g_w3lo[3*Dd*Pp];
__device__ __nv_bfloat16 g_wohi[Dd*Pp];       // Wo transposed split
__device__ __nv_bfloat16 g_wolo[Dd*Pp];

__device__ __nv_bfloat16 g_qkvhi[3*Bb*Hh*Ss*KD];  // q|k|v [B,H,S,Kd] (q scaled 1/8)
__device__ __nv_bfloat16 g_qkvlo[3*Bb*Hh*Ss*KD];
__device__ __nv_bfloat16 g_athi[Bb*Ss*Pp];        // attention out split [B,S,P]
__device__ __nv_bfloat16 g_atlo[Bb*Ss*Pp];

// ---------------------------------------------------------------------------
// helpers (base-target instructions only: mma.sync / ldmatrix / cp.async)
// ---------------------------------------------------------------------------
__device__ __forceinline__ uint32_t smem_u32(const void* p){
    uint32_t a;
    asm("{ .reg .u64 t; cvta.to.shared.u64 t, %1; cvt.u32.u64 %0, t; }" : "=r"(a) : "l"(p));
    return a;
}
__device__ __forceinline__ void cp16(uint32_t s, const void* g){
    asm volatile("cp.async.cg.shared.global [%0], [%1], 16;"
                 :: "r"(s), "l"(__cvta_generic_to_global(g)) : "memory");
}
__device__ __forceinline__ void ldsm4(uint32_t* d, uint32_t addr){
    asm volatile("ldmatrix.sync.aligned.m8n8.x4.shared.b16 {%0,%1,%2,%3}, [%4];"
                 : "=r"(d[0]), "=r"(d[1]), "=r"(d[2]), "=r"(d[3]) : "r"(addr));
}
__device__ __forceinline__ void ldsm4t(uint32_t* d, uint32_t addr){
    asm volatile("ldmatrix.sync.aligned.m8n8.x4.trans.shared.b16 {%0,%1,%2,%3}, [%4];"
                 : "=r"(d[0]), "=r"(d[1]), "=r"(d[2]), "=r"(d[3]) : "r"(addr));
}
__device__ __forceinline__ void mma16816(float* c, const uint32_t* a, const uint32_t* b){
    asm volatile("mma.sync.aligned.m16n8k16.row.col.f32.bf16.bf16.f32 "
                 "{%0,%1,%2,%3}, {%4,%5,%6,%7}, {%8,%9}, {%0,%1,%2,%3};"
                 : "+f"(c[0]), "+f"(c[1]), "+f"(c[2]), "+f"(c[3])
                 : "r"(a[0]), "r"(a[1]), "r"(a[2]), "r"(a[3]), "r"(b[0]), "r"(b[1]));
}
// swizzle for 128B rows (64 bf16), 16B chunk c (0..7)
__device__ __forceinline__ uint32_t swz128(int r, int c){
    return (uint32_t)(r * 128 + ((c ^ (r & 7)) << 4));
}
__device__ __forceinline__ uint32_t pack_bf16x2(float a, float b){
    __nv_bfloat162 t(__float2bfloat16(a), __float2bfloat16(b));
    return *reinterpret_cast<uint32_t*>(&t);
}

// ---------------------------------------------------------------------------
// fused split of q/k/v activations  (grid = 3 * 8192)
// ---------------------------------------------------------------------------
__global__ __launch_bounds__(256) void split3_kernel(
    const float* __restrict__ Xq, const float* __restrict__ Xk,
    const float* __restrict__ Xv,
    __nv_bfloat162* __restrict__ hi, __nv_bfloat162* __restrict__ lo)
{
    const int bx  = blockIdx.x;
    const int seg = bx >> 13;
    const int i   = (bx & 8191) * 256 + threadIdx.x;
    const float* X = (seg == 0) ? Xq : (seg == 1) ? Xk : Xv;
    float4 v = reinterpret_cast<const float4*>(X)[i];
    float f[4] = {v.x, v.y, v.z, v.w};
    __nv_bfloat16 h[4], l[4];
    #pragma unroll
    for (int j = 0; j < 4; j++){
        h[j] = __float2bfloat16(f[j]);
        l[j] = __float2bfloat16(f[j] - __bfloat162float(h[j]));
    }
    size_t o = (size_t)seg * (Mm * Dd / 2) + (size_t)i * 2;
    hi[o+0] = __nv_bfloat162(h[0], h[1]);
    hi[o+1] = __nv_bfloat162(h[2], h[3]);
    lo[o+0] = __nv_bfloat162(l[0], l[1]);
    lo[o+1] = __nv_bfloat162(l[2], l[3]);
}

// fused transpose+split of all 4 weights: grid (32, 32, 4)
__global__ __launch_bounds__(256) void tsplit4_kernel(
    const float* __restrict__ Wq, const float* __restrict__ Wk,
    const float* __restrict__ Wv, const float* __restrict__ Wo,
    __nv_bfloat16* __restrict__ w3h, __nv_bfloat16* __restrict__ w3l,
    __nv_bfloat16* __restrict__ woh, __nv_bfloat16* __restrict__ wol)
{
    __shared__ float t[32][33];
    const int seg = blockIdx.z;
    const float* W = (seg == 0) ? Wq : (seg == 1) ? Wk : (seg == 2) ? Wv : Wo;
    __nv_bfloat16* th = (seg < 3) ? w3h + (size_t)seg * Dd * Pp : woh;
    __nv_bfloat16* tl = (seg < 3) ? w3l + (size_t)seg * Dd * Pp : wol;

    const int n0 = blockIdx.x * 32, k0 = blockIdx.y * 32;
    const int tx = threadIdx.x, ty = threadIdx.y;     // 32 x 8
    #pragma unroll
    for (int r = 0; r < 4; r++)
        t[ty + 8*r][tx] = W[(size_t)(k0 + ty + 8*r) * Pp + n0 + tx];
    __syncthreads();
    #pragma unroll
    for (int r = 0; r < 4; r++){
        float v = t[tx][ty + 8*r];
        int n = n0 + ty + 8*r, k = k0 + tx;
        __nv_bfloat16 h = __float2bfloat16(v);
        th[(size_t)n * Dd + k] = h;
        tl[(size_t)n * Dd + k] = __float2bfloat16(v - __bfloat162float(h));
    }
}

// ---------------------------------------------------------------------------
// HMMA split-bf16 GEMM: 128x128 tile, BK=64, 256 threads, 3-stage cp.async,
// register-level fragment double-buffering, single barrier per k-chunk.
// ---------------------------------------------------------------------------
#define STB   65536
#define NSTG  3
#define NKI   (Dd / 64)        // 16

__device__ __forceinline__ void stage_load(
    uint32_t sb, const __nv_bfloat16* __restrict__ Ahi,
    const __nv_bfloat16* __restrict__ Alo,
    const __nv_bfloat16* __restrict__ Whi,
    const __nv_bfloat16* __restrict__ Wlo,
    int m0, int n0, int k0, int tid)
{
    const __nv_bfloat16* bases[4] = {Ahi, Alo, Whi, Wlo};
    #pragma unroll
    for (int tile = 0; tile < 4; tile++){
        const __nv_bfloat16* base = bases[tile];
        const int row0 = (tile < 2) ? m0 : n0;
        #pragma unroll
        for (int t = 0; t < 4; t++){
            int idx = tid + t * 256;
            int r = idx >> 3, c = idx & 7;
            cp16(sb + tile * 16384 + swz128(r, c),
                 base + (size_t)(row0 + r) * Dd + k0 + c * 8);
        }
    }
}

__global__ __launch_bounds__(256) void gemm_mma_kernel(
    const __nv_bfloat16* __restrict__ Ahi, const __nv_bfloat16* __restrict__ Alo,
    const __nv_bfloat16* __restrict__ Whi, const __nv_bfloat16* __restrict__ Wlo,
    const float* __restrict__ b0p, const float* __restrict__ b1p,
    const float* __restrict__ b2p,
    float* __restrict__ Cf, __nv_bfloat16* __restrict__ Chi,
    __nv_bfloat16* __restrict__ Clo, int mode)
{
    extern __shared__ char dsm[];
    const uint32_t sbase = smem_u32(dsm);

    const int tid  = threadIdx.x;
    const int lane = tid & 31;
    const int wid  = tid >> 5;
    const int wm   = wid & 1;
    const int wn   = wid >> 1;

    const int wsel = (mode == 1) ? (blockIdx.x >> 3) : 0;
    const int n0   = blockIdx.x * 128;
    const int m0   = blockIdx.y * 128;
    const int coln = n0 & 1023;
    const float* bias = (wsel == 0) ? b0p : (wsel == 1) ? b1p : b2p;
    const float scale = (mode == 1 && wsel == 0) ? 0.125f : 1.0f;
    const __nv_bfloat16* Ah = Ahi + (size_t)wsel * Mm * Dd;
    const __nv_bfloat16* Al = Alo + (size_t)wsel * Mm * Dd;

    float acc[4][4][4];
    #pragma unroll
    for (int i = 0; i < 4; i++)
        #pragma unroll
        for (int j = 0; j < 4; j++)
            #pragma unroll
            for (int k = 0; k < 4; k++) acc[i][j][k] = 0.f;

    stage_load(sbase,       Ah, Al, Whi, Wlo, m0, n0, 0,  tid);
    asm volatile("cp.async.commit_group;" ::: "memory");
    stage_load(sbase + STB, Ah, Al, Whi, Wlo, m0, n0, 64, tid);
    asm volatile("cp.async.commit_group;" ::: "memory");

    uint32_t ah[2][4][4], al[2][4][4], bh[2][8], bl[2][8];

    for (int kc = 0; kc < NKI; kc++){
        asm volatile("cp.async.wait_group 1;" ::: "memory");
        __syncthreads();

        if (kc + 2 < NKI)
            stage_load(sbase + (uint32_t)((kc + 2) % NSTG) * STB,
                       Ah, Al, Whi, Wlo, m0, n0, (kc + 2) * 64, tid);
        asm volatile("cp.async.commit_group;" ::: "memory");

        const uint32_t sb = sbase + (uint32_t)(kc % NSTG) * STB;

        #define LOAD_FRAGS(ks, buf)                                            \
        {                                                                      \
            _Pragma("unroll")                                                  \
            for (int mf = 0; mf < 4; mf++){                                    \
                int r = wm * 64 + mf * 16 + (lane & 15);                       \
                int c = (ks) * 2 + (lane >> 4);                                \
                uint32_t o = swz128(r, c);                                     \
                ldsm4(ah[buf][mf], sb + o);                                    \
                ldsm4(al[buf][mf], sb + 16384 + o);                            \
            }                                                                  \
            _Pragma("unroll")                                                  \
            for (int p = 0; p < 2; p++){                                       \
                int r = wn * 32 + p * 16 + ((lane >> 4) << 3) + (lane & 7);    \
                int c = (ks) * 2 + ((lane >> 3) & 1);                          \
                uint32_t o = swz128(r, c);                                     \
                ldsm4(&bh[buf][p*4], sb + 32768 + o);                          \
                ldsm4(&bl[buf][p*4], sb + 49152 + o);                          \
            }                                                                  \
        }

        LOAD_FRAGS(0, 0)
        #pragma unroll
        for (int ks = 0; ks < 4; ks++){
            const int cur = ks & 1;
            if (ks < 3) LOAD_FRAGS(ks + 1, cur ^ 1)
            #pragma unroll
            for (int mf = 0; mf < 4; mf++)
                #pragma unroll
                for (int nf = 0; nf < 4; nf++){
                    mma16816(acc[mf][nf], ah[cur][mf], &bh[cur][nf*2]);
                    mma16816(acc[mf][nf], ah[cur][mf], &bl[cur][nf*2]);
                    mma16816(acc[mf][nf], al[cur][mf], &bh[cur][nf*2]);
                }
        }
        #undef LOAD_FRAGS
    }

    #pragma unroll
    for (int mf = 0; mf < 4; mf++){
        #pragma unroll
        for (int nf = 0; nf < 4; nf++){
            const int col = coln + wn * 32 + nf * 8 + (lane & 3) * 2;
            const float bv0 = __ldg(&bias[col]), bv1 = __ldg(&bias[col + 1]);
            #pragma unroll
            for (int half = 0; half < 2; half++){
                const int m = m0 + wm * 64 + mf * 16 + (lane >> 2) + half * 8;
                float v0 = (acc[mf][nf][half*2 + 0] + bv0) * scale;
                float v1 = (acc[mf][nf][half*2 + 1] + bv1) * scale;
                if (mode == 0){
                    *(float2*)&Cf[(size_t)m * Pp + col] = make_float2(v0, v1);
                } else {
                    const int b  = m >> 11;
                    const int sq = m & 2047;
                    const int h  = col >> 6;
                    const int d  = col & 63;
                    size_t idx = (size_t)wsel * (Bb*Hh*Ss*KD)
                               + (((size_t)(b * Hh + h)) * Ss + sq) * KD + d;
                    __nv_bfloat16 h0 = __float2bfloat16(v0);
                    __nv_bfloat16 h1 = __float2bfloat16(v1);
                    *(__nv_bfloat162*)&Chi[idx] = __nv_bfloat162(h0, h1);
                    *(__nv_bfloat162*)&Clo[idx] = __nv_bfloat162(
                        __float2bfloat16(v0 - __bfloat162float(h0)),
                        __float2bfloat16(v1 - __bfloat162float(h1)));
                }
            }
        }
    }
}

// ---------------------------------------------------------------------------
// HMMA flash attention, causal + ALiBi, split-bf16 (3-term QK and PV).
// 128 threads / 64 q-rows per CTA, 2-stage KV (64KB smem) -> 3 CTAs/SM.
// Independent CTAs interleave softmax with MMA across the SM.
// ---------------------------------------------------------------------------
#define AT_STAGE 32768     // Khi|Klo|Vhi|Vlo, 8KB each

__device__ __forceinline__ void attn_load_kv(
    uint32_t st, const __nv_bfloat16* __restrict__ Khi,
    const __nv_bfloat16* __restrict__ Klo,
    const __nv_bfloat16* __restrict__ Vhi,
    const __nv_bfloat16* __restrict__ Vlo,
    size_t krow0, int jb, int tid)
{
    #pragma unroll
    for (int t = 0; t < 16; t++){
        int idx = tid + t * 128;          // 0..2047
        int tile = idx >> 9;
        int rem  = idx & 511;
        int r = rem >> 3, c = rem & 7;
        const __nv_bfloat16* base = (tile == 0) ? Khi : (tile == 1) ? Klo
                                   : (tile == 2) ? Vhi : Vlo;
        cp16(st + tile * 8192 + swz128(r, c),
             base + krow0 + (size_t)(jb + r) * KD + c * 8);
    }
}

__global__ __launch_bounds__(128, 3) void attn_mma_kernel(
    const __nv_bfloat16* __restrict__ Qhi, const __nv_bfloat16* __restrict__ Qlo,
    const __nv_bfloat16* __restrict__ Khi, const __nv_bfloat16* __restrict__ Klo,
    const __nv_bfloat16* __restrict__ Vhi, const __nv_bfloat16* __restrict__ Vlo,
    __nv_bfloat16* __restrict__ Ohi, __nv_bfloat16* __restrict__ Olo)
{
    extern __shared__ char dsm[];
    const uint32_t sb = smem_u32(dsm);

    const int tid  = threadIdx.x;
    const int lane = tid & 31;
    const int wid  = tid >> 5;           // 0..3
    const int bx   = (int)gridDim.x - 1 - (int)blockIdx.x;  // heavy CTAs first
    const int bh   = blockIdx.y;
    const int h    = bh & (Hh - 1);
    const int b    = bh >> 4;
    const int qb   = bx * 64;

    const size_t qrow0 = ((size_t)bh * Ss + qb) * KD;
    const size_t krow0 = ((size_t)bh * Ss) * KD;

    // ---- stage Q (hi 8KB | lo 8KB) into stage0 area, pull a-frags to regs ----
    #pragma unroll
    for (int t = 0; t < 8; t++){
        int idx = tid + t * 128;          // 0..1023
        int pre = idx >> 9;               // 0 hi, 1 lo
        int rem = idx & 511;
        int r = rem >> 3, c = rem & 7;    // r 0..63
        const __nv_bfloat16* base = pre ? Qlo : Qhi;
        cp16(sb + pre * 8192 + swz128(r, c), base + qrow0 + (size_t)r * KD + c * 8);
    }
    asm volatile("cp.async.commit_group;" ::: "memory");
    asm volatile("cp.async.wait_group 0;" ::: "memory");
    __syncthreads();

    uint32_t qh[4][4], ql[4][4];
    #pragma unroll
    for (int ks = 0; ks < 4; ks++){
        int r = wid * 16 + (lane & 15);   // 0..63
        int c = 2 * ks + (lane >> 4);
        uint32_t o = swz128(r, c);
        ldsm4(qh[ks], sb + o);
        ldsm4(ql[ks], sb + 8192 + o);
    }
    __syncthreads();   // Q reads done before KV preload overwrites

    const int ntiles = bx + 1;
    attn_load_kv(sb,            Khi, Klo, Vhi, Vlo, krow0, 0,  tid);
    asm volatile("cp.async.commit_group;" ::: "memory");
    attn_load_kv(sb + AT_STAGE, Khi, Klo, Vhi, Vlo, krow0, 64, tid);
    asm volatile("cp.async.commit_group;" ::: "memory");

    float oacc[8][4];
    #pragma unroll
    for (int i = 0; i < 8; i++)
        #pragma unroll
        for (int j = 0; j < 4; j++) oacc[i][j] = 0.f;

    float mr0 = -1e30f, mr1 = -1e30f, l0 = 0.f, l1 = 0.f;
    const float slope = exp2f(-0.5f * (float)(h + 1));
    const int qi0 = qb + wid * 16 + (lane >> 2);
    const int qi1 = qi0 + 8;
    const int jcol = (lane & 3) * 2;

    for (int jt = 0; jt < ntiles; jt++){
        asm volatile("cp.async.wait_group 1;" ::: "memory");
        __syncthreads();
        const uint32_t st = sb + (uint32_t)(jt & 1) * AT_STAGE;

        // ---- S = Q K^T (3-term), K-fragment double buffering ----
        float s[8][4];
        #pragma unroll
        for (int i = 0; i < 8; i++)
            #pragma unroll
            for (int j = 0; j < 4; j++) s[i][j] = 0.f;

        uint32_t kbh[2][16], kbl[2][16];
        #define LOADK(ks, buf)                                                 \
        {                                                                      \
            _Pragma("unroll")                                                  \
            for (int p = 0; p < 4; p++){                                       \
                int r = p * 16 + ((lane >> 4) << 3) + (lane & 7);              \
                int c = 2 * (ks) + ((lane >> 3) & 1);                          \
                uint32_t o = swz128(r, c);                                     \
                ldsm4(&kbh[buf][p*4], st + o);                                 \
                ldsm4(&kbl[buf][p*4], st + 8192 + o);                          \
            }                                                                  \
        }
        LOADK(0, 0)
        #pragma unroll
        for (int ks = 0; ks < 4; ks++){
            const int cur = ks & 1;
            if (ks < 3) LOADK(ks + 1, cur ^ 1)
            #pragma unroll
            for (int nf = 0; nf < 8; nf++){
                mma16816(s[nf], qh[ks], &kbh[cur][nf*2]);
                mma16816(s[nf], qh[ks], &kbl[cur][nf*2]);
                mma16816(s[nf], ql[ks], &kbh[cur][nf*2]);
            }
        }
        #undef LOADK

        // ---- bias + mask (mask only on the diagonal tile) ----
        const int jb = jt * 64;
        const bool need_mask = (jt == bx);
        #pragma unroll
        for (int nf = 0; nf < 8; nf++){
            const int jg0 = jb + nf * 8 + jcol;
            s[nf][0] += slope * (float)(qi0 - jg0);
            s[nf][1] += slope * (float)(qi0 - jg0 - 1);
            s[nf][2] += slope * (float)(qi1 - jg0);
            s[nf][3] += slope * (float)(qi1 - jg0 - 1);
            if (need_mask){
                if (jg0     > qi0) s[nf][0] = -1e30f;
                if (jg0 + 1 > qi0) s[nf][1] = -1e30f;
                if (jg0     > qi1) s[nf][2] = -1e30f;
                if (jg0 + 1 > qi1) s[nf][3] = -1e30f;
            }
        }

        // ---- online softmax ----
        float mx0 = -1e30f, mx1 = -1e30f;
        #pragma unroll
        for (int nf = 0; nf < 8; nf++){
            mx0 = fmaxf(mx0, fmaxf(s[nf][0], s[nf][1]));
            mx1 = fmaxf(mx1, fmaxf(s[nf][2], s[nf][3]));
        }
        mx0 = fmaxf(mx0, __shfl_xor_sync(0xffffffffu, mx0, 1));
        mx0 = fmaxf(mx0, __shfl_xor_sync(0xffffffffu, mx0, 2));
        mx1 = fmaxf(mx1, __shfl_xor_sync(0xffffffffu, mx1, 1));
        mx1 = fmaxf(mx1, __shfl_xor_sync(0xffffffffu, mx1, 2));

        const float mn0 = fmaxf(mr0, mx0);
        const float mn1 = fmaxf(mr1, mx1);
        const float c0 = __expf(mr0 - mn0);
        const float c1 = __expf(mr1 - mn1);
        l0 *= c0; l1 *= c1;
        #pragma unroll
        for (int df = 0; df < 8; df++){
            oacc[df][0] *= c0; oacc[df][1] *= c0;
            oacc[df][2] *= c1; oacc[df][3] *= c1;
        }
        mr0 = mn0; mr1 = mn1;

        // ---- p = exp, split, repack into PV A-frags ----
        uint32_t pah[4][4], pal[4][4];
        #pragma unroll
        for (int nf = 0; nf < 8; nf++){
            float p0 = __expf(s[nf][0] - mn0);
            float p1 = __expf(s[nf][1] - mn0);
            float p2 = __expf(s[nf][2] - mn1);
            float p3 = __expf(s[nf][3] - mn1);
            l0 += p0 + p1; l1 += p2 + p3;
            __nv_bfloat16 h0 = __float2bfloat16(p0), h1 = __float2bfloat16(p1);
            __nv_bfloat16 h2 = __float2bfloat16(p2), h3 = __float2bfloat16(p3);
            const int ks  = nf >> 1;
            const int pos = (nf & 1) * 2;
            __nv_bfloat162 th01(h0, h1), th23(h2, h3);
            pah[ks][pos + 0] = *reinterpret_cast<uint32_t*>(&th01);
            pah[ks][pos + 1] = *reinterpret_cast<uint32_t*>(&th23);
            pal[ks][pos + 0] = pack_bf16x2(p0 - __bfloat162float(h0),
                                           p1 - __bfloat162float(h1));
            pal[ks][pos + 1] = pack_bf16x2(p2 - __bfloat162float(h2),
                                           p3 - __bfloat162float(h3));
        }

        // ---- O += P V (3-term), V-fragment double buffering ----
        uint32_t vbh[2][16], vbl[2][16];
        #define LOADV(ks, buf)                                                 \
        {                                                                      \
            _Pragma("unroll")                                                  \
            for (int g = 0; g < 4; g++){                                       \
                int r = (ks) * 16 + ((lane >> 3) & 1) * 8 + (lane & 7);        \
                int c = 2 * g + (lane >> 4);                                   \
                uint32_t o = swz128(r, c);                                     \
                ldsm4t(&vbh[buf][g*4], st + 16384 + o);                        \
                ldsm4t(&vbl[buf][g*4], st + 24576 + o);                        \
            }                                                                  \
        }
        LOADV(0, 0)
        #pragma unroll
        for (int ks = 0; ks < 4; ks++){
            const int cur = ks & 1;
            if (ks < 3) LOADV(ks + 1, cur ^ 1)
            #pragma unroll
            for (int df = 0; df < 8; df++){
                mma16816(oacc[df], pah[ks], &vbh[cur][df*2]);
                mma16816(oacc[df], pah[ks], &vbl[cur][df*2]);
                mma16816(oacc[df], pal[ks], &vbh[cur][df*2]);
            }
        }
        #undef LOADV

        // refill the just-consumed stage for tile jt+2
        __syncthreads();
        if (jt + 2 < ntiles)
            attn_load_kv(sb + (uint32_t)(jt & 1) * AT_STAGE,
                         Khi, Klo, Vhi, Vlo, krow0, (jt + 2) * 64, tid);
        asm volatile("cp.async.commit_group;" ::: "memory");
    }

    // ---- epilogue: normalize, split hi/lo bf16, store [B,S,P] ----
    l0 += __shfl_xor_sync(0xffffffffu, l0, 1);
    l0 += __shfl_xor_sync(0xffffffffu, l0, 2);
    l1 += __shfl_xor_sync(0xffffffffu, l1, 1);
    l1 += __shfl_xor_sync(0xffffffffu, l1, 2);
    const float inv0 = 1.f / l0, inv1 = 1.f / l1;

    const size_t orow0 = ((size_t)(b * Ss + qi0)) * Pp + h * KD;
    const size_t orow1 = ((size_t)(b * Ss + qi1)) * Pp + h * KD;
    #pragma unroll
    for (int df = 0; df < 8; df++){
        const int d = df * 8 + jcol;
        float v0 = oacc[df][0] * inv0, v1 = oacc[df][1] * inv0;
        float v2 = oacc[df][2] * inv1, v3 = oacc[df][3] * inv1;
        __nv_bfloat16 h0 = __float2bfloat16(v0), h1 = __float2bfloat16(v1);
        __nv_bfloat16 h2 = __float2bfloat16(v2), h3 = __float2bfloat16(v3);
        *(__nv_bfloat162*)&Ohi[orow0 + d] = __nv_bfloat162(h0, h1);
        *(__nv_bfloat162*)&Ohi[orow1 + d] = __nv_bfloat162(h2, h3);
        *(__nv_bfloat162*)&Olo[orow0 + d] = __nv_bfloat162(
            __float2bfloat16(v0 - __bfloat162float(h0)),
            __float2bfloat16(v1 - __bfloat162float(h1)));
        *(__nv_bfloat162*)&Olo[orow1 + d] = __nv_bfloat162(
            __float2bfloat16(v2 - __bfloat162float(h2)),
            __float2bfloat16(v3 - __bfloat162float(h3)));
    }
}

// ---------------------------------------------------------------------------
extern "C" void kernel_launch(void* const* d_in, const int* in_sizes, int n_in,
                              void* d_out, int out_size)
{
    const float* query = (const float*)d_in[0];
    const float* key   = (const float*)d_in[1];
    const float* value = (const float*)d_in[2];
    const float* Wq    = (const float*)d_in[3];
    const float* bq    = (const float*)d_in[4];
    const float* Wk    = (const float*)d_in[5];
    const float* bk    = (const float*)d_in[6];
    const float* Wv    = (const float*)d_in[7];
    const float* bv    = (const float*)d_in[8];
    const float* Wo    = (const float*)d_in[9];
    const float* bo    = (const float*)d_in[10];
    float* out = (float*)d_out;

    __nv_bfloat16 *a3hi, *a3lo, *w3hi, *w3lo, *wohi, *wolo;
    __nv_bfloat16 *qkvhi, *qkvlo, *athi, *atlo;
    cudaGetSymbolAddress((void**)&a3hi,  g_a3hi);
    cudaGetSymbolAddress((void**)&a3lo,  g_a3lo);
    cudaGetSymbolAddress((void**)&w3hi,  g_w3hi);
    cudaGetSymbolAddress((void**)&w3lo,  g_w3lo);
    cudaGetSymbolAddress((void**)&wohi,  g_wohi);
    cudaGetSymbolAddress((void**)&wolo,  g_wolo);
    cudaGetSymbolAddress((void**)&qkvhi, g_qkvhi);
    cudaGetSymbolAddress((void**)&qkvlo, g_qkvlo);
    cudaGetSymbolAddress((void**)&athi,  g_athi);
    cudaGetSymbolAddress((void**)&atlo,  g_atlo);

    static int attr_set = 0;
    const int gemm_smem = NSTG * STB;        // 192 KB
    const int attn_smem = 2 * AT_STAGE;      // 64 KB -> 3 CTAs/SM
    if (!attr_set) {
        cudaFuncSetAttribute(gemm_mma_kernel,
                             cudaFuncAttributeMaxDynamicSharedMemorySize, gemm_smem);
        cudaFuncSetAttribute(attn_mma_kernel,
                             cudaFuncAttributeMaxDynamicSharedMemorySize, attn_smem);
        attr_set = 1;
    }

    // fused activation split (q|k|v) + fused weight transpose/split (4 weights)
    split3_kernel<<<3 * 8192, 256>>>(query, key, value,
                                     (__nv_bfloat162*)a3hi, (__nv_bfloat162*)a3lo);
    dim3 tgrid(Pp / 32, Dd / 32, 4);
    dim3 tblk(32, 8);
    tsplit4_kernel<<<tgrid, tblk>>>(Wq, Wk, Wv, Wo, w3hi, w3lo, wohi, wolo);

    // fused QKV projection: grid (24, 64)
    dim3 qkvgrid(3 * Pp / 128, Mm / 128);
    gemm_mma_kernel<<<qkvgrid, 256, gemm_smem>>>(
        a3hi, a3lo, w3hi, w3lo, bq, bk, bv,
        nullptr, qkvhi, qkvlo, 1);

    // attention: grid (32, 64), 128 threads, 64 q-rows per CTA
    const size_t seg = (size_t)Bb * Hh * Ss * KD;
    dim3 agrid(Ss / 64, Bb * Hh);
    attn_mma_kernel<<<agrid, 128, attn_smem>>>(
        qkvhi, qkvlo, qkvhi + seg, qkvlo + seg, qkvhi + 2*seg, qkvlo + 2*seg,
        athi, atlo);

    // output projection: grid (8, 64)
    dim3 ogrid(Pp / 128, Mm / 128);
    gemm_mma_kernel<<<ogrid, 256, gemm_smem>>>(
        athi, atlo, wohi, wolo, bo, bo, bo,
        out, nullptr, nullptr, 0);
}

// round 17
// speedup vs baseline: 1.4595x; 1.4595x over previous
#include <cuda_runtime.h>
#include <cuda_bf16.h>
#include <math.h>
#include <stdint.h>

#define Bb 4
#define Ss 2048
#define Dd 1024
#define Hh 16
#define KD 64
#define Pp 1024
#define Mm (Bb*Ss)          // 8192
#define LOG2E 1.44269504088896f

// ---------------- scratch (static __device__ per allocation rules) ----------
__device__ __nv_bfloat16 g_a3hi[3*Mm*Dd];     // q|k|v activation splits
__device__ __nv_bfloat16 g_a3lo[3*Mm*Dd];
__device__ __nv_bfloat16 g_w3hi[3*Dd*Pp];     // Wq|Wk|Wv transposed splits [N][K]
__device__ __nv_bfloat16 g_w3lo[3*Dd*Pp];
__device__ __nv_bfloat16 g_wohi[Dd*Pp];       // Wo transposed split
__device__ __nv_bfloat16 g_wolo[Dd*Pp];

__device__ __nv_bfloat16 g_qkvhi[3*Bb*Hh*Ss*KD];  // q|k|v [B,H,S,Kd] (q scaled)
__device__ __nv_bfloat16 g_qkvlo[3*Bb*Hh*Ss*KD];
__device__ __nv_bfloat16 g_athi[Bb*Ss*Pp];        // attention out split [B,S,P]
__device__ __nv_bfloat16 g_atlo[Bb*Ss*Pp];

// ---------------------------------------------------------------------------
// helpers (base-target instructions only: mma.sync / ldmatrix / cp.async)
// ---------------------------------------------------------------------------
__device__ __forceinline__ uint32_t smem_u32(const void* p){
    uint32_t a;
    asm("{ .reg .u64 t; cvta.to.shared.u64 t, %1; cvt.u32.u64 %0, t; }" : "=r"(a) : "l"(p));
    return a;
}
__device__ __forceinline__ void cp16(uint32_t s, const void* g){
    asm volatile("cp.async.cg.shared.global [%0], [%1], 16;"
                 :: "r"(s), "l"(__cvta_generic_to_global(g)) : "memory");
}
__device__ __forceinline__ void ldsm4(uint32_t* d, uint32_t addr){
    asm volatile("ldmatrix.sync.aligned.m8n8.x4.shared.b16 {%0,%1,%2,%3}, [%4];"
                 : "=r"(d[0]), "=r"(d[1]), "=r"(d[2]), "=r"(d[3]) : "r"(addr));
}
__device__ __forceinline__ void ldsm4t(uint32_t* d, uint32_t addr){
    asm volatile("ldmatrix.sync.aligned.m8n8.x4.trans.shared.b16 {%0,%1,%2,%3}, [%4];"
                 : "=r"(d[0]), "=r"(d[1]), "=r"(d[2]), "=r"(d[3]) : "r"(addr));
}
__device__ __forceinline__ void mma16816(float* c, const uint32_t* a, const uint32_t* b){
    asm volatile("mma.sync.aligned.m16n8k16.row.col.f32.bf16.bf16.f32 "
                 "{%0,%1,%2,%3}, {%4,%5,%6,%7}, {%8,%9}, {%0,%1,%2,%3};"
                 : "+f"(c[0]), "+f"(c[1]), "+f"(c[2]), "+f"(c[3])
                 : "r"(a[0]), "r"(a[1]), "r"(a[2]), "r"(a[3]), "r"(b[0]), "r"(b[1]));
}
// swizzle for 128B rows (64 bf16), 16B chunk c (0..7)
__device__ __forceinline__ uint32_t swz128(int r, int c){
    return (uint32_t)(r * 128 + ((c ^ (r & 7)) << 4));
}
__device__ __forceinline__ uint32_t pack_bf16x2(float a, float b){
    __nv_bfloat162 t(__float2bfloat16(a), __float2bfloat16(b));
    return *reinterpret_cast<uint32_t*>(&t);
}

// ---------------------------------------------------------------------------
// fused split of q/k/v activations  (grid = 3 * 8192)
// ---------------------------------------------------------------------------
__global__ __launch_bounds__(256) void split3_kernel(
    const float* __restrict__ Xq, const float* __restrict__ Xk,
    const float* __restrict__ Xv,
    __nv_bfloat162* __restrict__ hi, __nv_bfloat162* __restrict__ lo)
{
    const int bx  = blockIdx.x;
    const int seg = bx >> 13;
    const int i   = (bx & 8191) * 256 + threadIdx.x;
    const float* X = (seg == 0) ? Xq : (seg == 1) ? Xk : Xv;
    float4 v = reinterpret_cast<const float4*>(X)[i];
    float f[4] = {v.x, v.y, v.z, v.w};
    __nv_bfloat16 h[4], l[4];
    #pragma unroll
    for (int j = 0; j < 4; j++){
        h[j] = __float2bfloat16(f[j]);
        l[j] = __float2bfloat16(f[j] - __bfloat162float(h[j]));
    }
    size_t o = (size_t)seg * (Mm * Dd / 2) + (size_t)i * 2;
    hi[o+0] = __nv_bfloat162(h[0], h[1]);
    hi[o+1] = __nv_bfloat162(h[2], h[3]);
    lo[o+0] = __nv_bfloat162(l[0], l[1]);
    lo[o+1] = __nv_bfloat162(l[2], l[3]);
}

// fused transpose+split of all 4 weights: grid (32, 32, 4)
__global__ __launch_bounds__(256) void tsplit4_kernel(
    const float* __restrict__ Wq, const float* __restrict__ Wk,
    const float* __restrict__ Wv, const float* __restrict__ Wo,
    __nv_bfloat16* __restrict__ w3h, __nv_bfloat16* __restrict__ w3l,
    __nv_bfloat16* __restrict__ woh, __nv_bfloat16* __restrict__ wol)
{
    __shared__ float t[32][33];
    const int seg = blockIdx.z;
    const float* W = (seg == 0) ? Wq : (seg == 1) ? Wk : (seg == 2) ? Wv : Wo;
    __nv_bfloat16* th = (seg < 3) ? w3h + (size_t)seg * Dd * Pp : woh;
    __nv_bfloat16* tl = (seg < 3) ? w3l + (size_t)seg * Dd * Pp : wol;

    const int n0 = blockIdx.x * 32, k0 = blockIdx.y * 32;
    const int tx = threadIdx.x, ty = threadIdx.y;     // 32 x 8
    #pragma unroll
    for (int r = 0; r < 4; r++)
        t[ty + 8*r][tx] = W[(size_t)(k0 + ty + 8*r) * Pp + n0 + tx];
    __syncthreads();
    #pragma unroll
    for (int r = 0; r < 4; r++){
        float v = t[tx][ty + 8*r];
        int n = n0 + ty + 8*r, k = k0 + tx;
        __nv_bfloat16 h = __float2bfloat16(v);
        th[(size_t)n * Dd + k] = h;
        tl[(size_t)n * Dd + k] = __float2bfloat16(v - __bfloat162float(h));
    }
}

// ---------------------------------------------------------------------------
// HMMA split-bf16 GEMM: 128x128 tile, BK=64, 256 threads, 3-stage cp.async,
// register-level fragment double-buffering.  (R14 winner, unchanged.)
// ---------------------------------------------------------------------------
#define STB   65536
#define NSTG  3
#define NKI   (Dd / 64)        // 16

__device__ __forceinline__ void stage_load(
    uint32_t sb, const __nv_bfloat16* __restrict__ Ahi,
    const __nv_bfloat16* __restrict__ Alo,
    const __nv_bfloat16* __restrict__ Whi,
    const __nv_bfloat16* __restrict__ Wlo,
    int m0, int n0, int k0, int tid)
{
    const __nv_bfloat16* bases[4] = {Ahi, Alo, Whi, Wlo};
    #pragma unroll
    for (int tile = 0; tile < 4; tile++){
        const __nv_bfloat16* base = bases[tile];
        const int row0 = (tile < 2) ? m0 : n0;
        #pragma unroll
        for (int t = 0; t < 4; t++){
            int idx = tid + t * 256;
            int r = idx >> 3, c = idx & 7;
            cp16(sb + tile * 16384 + swz128(r, c),
                 base + (size_t)(row0 + r) * Dd + k0 + c * 8);
        }
    }
}

__global__ __launch_bounds__(256) void gemm_mma_kernel(
    const __nv_bfloat16* __restrict__ Ahi, const __nv_bfloat16* __restrict__ Alo,
    const __nv_bfloat16* __restrict__ Whi, const __nv_bfloat16* __restrict__ Wlo,
    const float* __restrict__ b0p, const float* __restrict__ b1p,
    const float* __restrict__ b2p,
    float* __restrict__ Cf, __nv_bfloat16* __restrict__ Chi,
    __nv_bfloat16* __restrict__ Clo, int mode)
{
    extern __shared__ char dsm[];
    const uint32_t sbase = smem_u32(dsm);

    const int tid  = threadIdx.x;
    const int lane = tid & 31;
    const int wid  = tid >> 5;
    const int wm   = wid & 1;
    const int wn   = wid >> 1;

    const int wsel = (mode == 1) ? (blockIdx.x >> 3) : 0;
    const int n0   = blockIdx.x * 128;
    const int m0   = blockIdx.y * 128;
    const int coln = n0 & 1023;
    const float* bias = (wsel == 0) ? b0p : (wsel == 1) ? b1p : b2p;
    // Q gets 1/8 (logit scale) * LOG2E (base-2 softmax domain) folded in.
    const float scale = (mode == 1 && wsel == 0) ? 0.125f * LOG2E : 1.0f;
    const __nv_bfloat16* Ah = Ahi + (size_t)wsel * Mm * Dd;
    const __nv_bfloat16* Al = Alo + (size_t)wsel * Mm * Dd;

    float acc[4][4][4];
    #pragma unroll
    for (int i = 0; i < 4; i++)
        #pragma unroll
        for (int j = 0; j < 4; j++)
            #pragma unroll
            for (int k = 0; k < 4; k++) acc[i][j][k] = 0.f;

    stage_load(sbase,       Ah, Al, Whi, Wlo, m0, n0, 0,  tid);
    asm volatile("cp.async.commit_group;" ::: "memory");
    stage_load(sbase + STB, Ah, Al, Whi, Wlo, m0, n0, 64, tid);
    asm volatile("cp.async.commit_group;" ::: "memory");

    uint32_t ah[2][4][4], al[2][4][4], bh[2][8], bl[2][8];

    for (int kc = 0; kc < NKI; kc++){
        asm volatile("cp.async.wait_group 1;" ::: "memory");
        __syncthreads();

        if (kc + 2 < NKI)
            stage_load(sbase + (uint32_t)((kc + 2) % NSTG) * STB,
                       Ah, Al, Whi, Wlo, m0, n0, (kc + 2) * 64, tid);
        asm volatile("cp.async.commit_group;" ::: "memory");

        const uint32_t sb = sbase + (uint32_t)(kc % NSTG) * STB;

        #define LOAD_FRAGS(ks, buf)                                            \
        {                                                                      \
            _Pragma("unroll")                                                  \
            for (int mf = 0; mf < 4; mf++){                                    \
                int r = wm * 64 + mf * 16 + (lane & 15);                       \
                int c = (ks) * 2 + (lane >> 4);                                \
                uint32_t o = swz128(r, c);                                     \
                ldsm4(ah[buf][mf], sb + o);                                    \
                ldsm4(al[buf][mf], sb + 16384 + o);                            \
            }                                                                  \
            _Pragma("unroll")                                                  \
            for (int p = 0; p < 2; p++){                                       \
                int r = wn * 32 + p * 16 + ((lane >> 4) << 3) + (lane & 7);    \
                int c = (ks) * 2 + ((lane >> 3) & 1);                          \
                uint32_t o = swz128(r, c);                                     \
                ldsm4(&bh[buf][p*4], sb + 32768 + o);                          \
                ldsm4(&bl[buf][p*4], sb + 49152 + o);                          \
            }                                                                  \
        }

        LOAD_FRAGS(0, 0)
        #pragma unroll
        for (int ks = 0; ks < 4; ks++){
            const int cur = ks & 1;
            if (ks < 3) LOAD_FRAGS(ks + 1, cur ^ 1)
            #pragma unroll
            for (int mf = 0; mf < 4; mf++)
                #pragma unroll
                for (int nf = 0; nf < 4; nf++){
                    mma16816(acc[mf][nf], ah[cur][mf], &bh[cur][nf*2]);
                    mma16816(acc[mf][nf], ah[cur][mf], &bl[cur][nf*2]);
                    mma16816(acc[mf][nf], al[cur][mf], &bh[cur][nf*2]);
                }
        }
        #undef LOAD_FRAGS
        __syncthreads();
    }

    #pragma unroll
    for (int mf = 0; mf < 4; mf++){
        #pragma unroll
        for (int nf = 0; nf < 4; nf++){
            const int col = coln + wn * 32 + nf * 8 + (lane & 3) * 2;
            const float bv0 = __ldg(&bias[col]), bv1 = __ldg(&bias[col + 1]);
            #pragma unroll
            for (int half = 0; half < 2; half++){
                const int m = m0 + wm * 64 + mf * 16 + (lane >> 2) + half * 8;
                float v0 = (acc[mf][nf][half*2 + 0] + bv0) * scale;
                float v1 = (acc[mf][nf][half*2 + 1] + bv1) * scale;
                if (mode == 0){
                    *(float2*)&Cf[(size_t)m * Pp + col] = make_float2(v0, v1);
                } else {
                    const int b  = m >> 11;
                    const int sq = m & 2047;
                    const int h  = col >> 6;
                    const int d  = col & 63;
                    size_t idx = (size_t)wsel * (Bb*Hh*Ss*KD)
                               + (((size_t)(b * Hh + h)) * Ss + sq) * KD + d;
                    __nv_bfloat16 h0 = __float2bfloat16(v0);
                    __nv_bfloat16 h1 = __float2bfloat16(v1);
                    *(__nv_bfloat162*)&Chi[idx] = __nv_bfloat162(h0, h1);
                    *(__nv_bfloat162*)&Clo[idx] = __nv_bfloat162(
                        __float2bfloat16(v0 - __bfloat162float(h0)),
                        __float2bfloat16(v1 - __bfloat162float(h1)));
                }
            }
        }
    }
}

// ---------------------------------------------------------------------------
// HMMA flash attention, causal + ALiBi, split-bf16 (3-term QK and PV).
// R14 winner structure: 256 threads, 128 q-rows, 2-stage KV (64KB).
// Softmax in base-2 domain; ALiBi reduced to column-only bias
// (the slope*qi row term is constant per row and cancels in softmax).
// ---------------------------------------------------------------------------
#define AT_STAGE 32768

__device__ __forceinline__ void attn_load_kv(
    uint32_t st, const __nv_bfloat16* __restrict__ Khi,
    const __nv_bfloat16* __restrict__ Klo,
    const __nv_bfloat16* __restrict__ Vhi,
    const __nv_bfloat16* __restrict__ Vlo,
    size_t krow0, int jb, int tid)
{
    #pragma unroll
    for (int t = 0; t < 8; t++){
        int idx = tid + t * 256;
        int tile = idx >> 9;
        int rem  = idx & 511;
        int r = rem >> 3, c = rem & 7;
        const __nv_bfloat16* base = (tile == 0) ? Khi : (tile == 1) ? Klo
                                   : (tile == 2) ? Vhi : Vlo;
        cp16(st + tile * 8192 + swz128(r, c),
             base + krow0 + (size_t)(jb + r) * KD + c * 8);
    }
}

__global__ __launch_bounds__(256) void attn_mma_kernel(
    const __nv_bfloat16* __restrict__ Qhi, const __nv_bfloat16* __restrict__ Qlo,
    const __nv_bfloat16* __restrict__ Khi, const __nv_bfloat16* __restrict__ Klo,
    const __nv_bfloat16* __restrict__ Vhi, const __nv_bfloat16* __restrict__ Vlo,
    __nv_bfloat16* __restrict__ Ohi, __nv_bfloat16* __restrict__ Olo)
{
    extern __shared__ char dsm[];
    const uint32_t sb = smem_u32(dsm);

    const int tid  = threadIdx.x;
    const int lane = tid & 31;
    const int wid  = tid >> 5;
    const int bx   = blockIdx.x;
    const int bh   = blockIdx.y;
    const int h    = bh & (Hh - 1);
    const int b    = bh >> 4;
    const int qb   = bx * 128;

    const size_t qrow0 = ((size_t)bh * Ss + qb) * KD;
    const size_t krow0 = ((size_t)bh * Ss) * KD;

    // ---- stage Q (hi 16KB | lo 16KB) into stage0, pull a-frags to regs ----
    #pragma unroll
    for (int t = 0; t < 8; t++){
        int idx = tid + t * 256;
        int pre = idx >> 10;
        int rem = idx & 1023;
        int r = rem >> 3, c = rem & 7;
        const __nv_bfloat16* base = pre ? Qlo : Qhi;
        cp16(sb + pre * 16384 + swz128(r, c), base + qrow0 + (size_t)r * KD + c * 8);
    }
    asm volatile("cp.async.commit_group;" ::: "memory");
    asm volatile("cp.async.wait_group 0;" ::: "memory");
    __syncthreads();

    uint32_t qh[4][4], ql[4][4];
    #pragma unroll
    for (int ks = 0; ks < 4; ks++){
        int r = wid * 16 + (lane & 15);
        int c = 2 * ks + (lane >> 4);
        uint32_t o = swz128(r, c);
        ldsm4(qh[ks], sb + o);
        ldsm4(ql[ks], sb + 16384 + o);
    }
    __syncthreads();   // all reads of stage0 done before K/V overwrite

    const int ntiles = 2 * bx + 2;
    attn_load_kv(sb,            Khi, Klo, Vhi, Vlo, krow0, 0,  tid);
    asm volatile("cp.async.commit_group;" ::: "memory");
    attn_load_kv(sb + AT_STAGE, Khi, Klo, Vhi, Vlo, krow0, 64, tid);
    asm volatile("cp.async.commit_group;" ::: "memory");

    float oacc[8][4];
    #pragma unroll
    for (int i = 0; i < 8; i++)
        #pragma unroll
        for (int j = 0; j < 4; j++) oacc[i][j] = 0.f;

    float mr0 = -1e30f, mr1 = -1e30f, l0 = 0.f, l1 = 0.f;
    // base-2 slope; row term slope*qi cancels in softmax -> column bias only
    const float slope2 = exp2f(-0.5f * (float)(h + 1)) * LOG2E;
    const int qi0 = qb + wid * 16 + (lane >> 2);
    const int qi1 = qi0 + 8;
    const int jcol = (lane & 3) * 2;

    for (int jt = 0; jt < ntiles; jt++){
        asm volatile("cp.async.wait_group 1;" ::: "memory");
        __syncthreads();
        const uint32_t st = sb + (uint32_t)(jt & 1) * AT_STAGE;

        // ---- S = Q K^T (3-term) ----
        float s[8][4];
        #pragma unroll
        for (int i = 0; i < 8; i++)
            #pragma unroll
            for (int j = 0; j < 4; j++) s[i][j] = 0.f;

        #pragma unroll
        for (int ks = 0; ks < 4; ks++){
            uint32_t kbh[16], kbl[16];
            #pragma unroll
            for (int p = 0; p < 4; p++){
                int r = p * 16 + ((lane >> 4) << 3) + (lane & 7);
                int c = 2 * ks + ((lane >> 3) & 1);
                uint32_t o = swz128(r, c);
                ldsm4(&kbh[p*4], st + o);
                ldsm4(&kbl[p*4], st + 8192 + o);
            }
            #pragma unroll
            for (int nf = 0; nf < 8; nf++){
                mma16816(s[nf], qh[ks], &kbh[nf*2]);
                mma16816(s[nf], qh[ks], &kbl[nf*2]);
                mma16816(s[nf], ql[ks], &kbh[nf*2]);
            }
        }

        // ---- column-only ALiBi bias + causal mask ----
        const int jb = jt * 64;
        const bool need_mask = (jt >= 2 * bx);
        #pragma unroll
        for (int nf = 0; nf < 8; nf++){
            const int jg0 = jb + nf * 8 + jcol;
            const float cb0 = -slope2 * (float)jg0;
            const float cb1 = -slope2 * (float)(jg0 + 1);
            s[nf][0] += cb0;
            s[nf][1] += cb1;
            s[nf][2] += cb0;
            s[nf][3] += cb1;
            if (need_mask){
                if (jg0     > qi0) s[nf][0] = -1e30f;
                if (jg0 + 1 > qi0) s[nf][1] = -1e30f;
                if (jg0     > qi1) s[nf][2] = -1e30f;
                if (jg0 + 1 > qi1) s[nf][3] = -1e30f;
            }
        }

        // ---- online softmax (base-2 domain) ----
        float mx0 = -1e30f, mx1 = -1e30f;
        #pragma unroll
        for (int nf = 0; nf < 8; nf++){
            mx0 = fmaxf(mx0, fmaxf(s[nf][0], s[nf][1]));
            mx1 = fmaxf(mx1, fmaxf(s[nf][2], s[nf][3]));
        }
        mx0 = fmaxf(mx0, __shfl_xor_sync(0xffffffffu, mx0, 1));
        mx0 = fmaxf(mx0, __shfl_xor_sync(0xffffffffu, mx0, 2));
        mx1 = fmaxf(mx1, __shfl_xor_sync(0xffffffffu, mx1, 1));
        mx1 = fmaxf(mx1, __shfl_xor_sync(0xffffffffu, mx1, 2));

        const float mn0 = fmaxf(mr0, mx0);
        const float mn1 = fmaxf(mr1, mx1);
        const float c0 = exp2f(mr0 - mn0);
        const float c1 = exp2f(mr1 - mn1);
        l0 *= c0; l1 *= c1;
        #pragma unroll
        for (int df = 0; df < 8; df++){
            oacc[df][0] *= c0; oacc[df][1] *= c0;
            oacc[df][2] *= c1; oacc[df][3] *= c1;
        }
        mr0 = mn0; mr1 = mn1;

        // ---- p = exp2, split, repack into PV A-frags ----
        uint32_t pah[4][4], pal[4][4];
        #pragma unroll
        for (int nf = 0; nf < 8; nf++){
            float p0 = exp2f(s[nf][0] - mn0);
            float p1 = exp2f(s[nf][1] - mn0);
            float p2 = exp2f(s[nf][2] - mn1);
            float p3 = exp2f(s[nf][3] - mn1);
            l0 += p0 + p1; l1 += p2 + p3;
            __nv_bfloat16 h0 = __float2bfloat16(p0), h1 = __float2bfloat16(p1);
            __nv_bfloat16 h2 = __float2bfloat16(p2), h3 = __float2bfloat16(p3);
            const int ks  = nf >> 1;
            const int pos = (nf & 1) * 2;
            __nv_bfloat162 th01(h0, h1), th23(h2, h3);
            pah[ks][pos + 0] = *reinterpret_cast<uint32_t*>(&th01);
            pah[ks][pos + 1] = *reinterpret_cast<uint32_t*>(&th23);
            pal[ks][pos + 0] = pack_bf16x2(p0 - __bfloat162float(h0),
                                           p1 - __bfloat162float(h1));
            pal[ks][pos + 1] = pack_bf16x2(p2 - __bfloat162float(h2),
                                           p3 - __bfloat162float(h3));
        }

        // ---- O += P V (3-term), V via ldmatrix.trans ----
        #pragma unroll
        for (int ks = 0; ks < 4; ks++){
            uint32_t vbh[16], vbl[16];
            #pragma unroll
            for (int g = 0; g < 4; g++){
                int r = ks * 16 + ((lane >> 3) & 1) * 8 + (lane & 7);
                int c = 2 * g + (lane >> 4);
                uint32_t o = swz128(r, c);
                ldsm4t(&vbh[g*4], st + 16384 + o);
                ldsm4t(&vbl[g*4], st + 24576 + o);
            }
            #pragma unroll
            for (int df = 0; df < 8; df++){
                mma16816(oacc[df], pah[ks], &vbh[df*2]);
                mma16816(oacc[df], pah[ks], &vbl[df*2]);
                mma16816(oacc[df], pal[ks], &vbh[df*2]);
            }
        }

        __syncthreads();   // stage fully consumed before refill
        if (jt + 2 < ntiles)
            attn_load_kv(sb + (uint32_t)(jt & 1) * AT_STAGE,
                         Khi, Klo, Vhi, Vlo, krow0, (jt + 2) * 64, tid);
        asm volatile("cp.async.commit_group;" ::: "memory");
    }

    // ---- epilogue: normalize, split hi/lo bf16, store [B,S,P] ----
    l0 += __shfl_xor_sync(0xffffffffu, l0, 1);
    l0 += __shfl_xor_sync(0xffffffffu, l0, 2);
    l1 += __shfl_xor_sync(0xffffffffu, l1, 1);
    l1 += __shfl_xor_sync(0xffffffffu, l1, 2);
    const float inv0 = 1.f / l0, inv1 = 1.f / l1;

    const size_t orow0 = ((size_t)(b * Ss + qi0)) * Pp + h * KD;
    const size_t orow1 = ((size_t)(b * Ss + qi1)) * Pp + h * KD;
    #pragma unroll
    for (int df = 0; df < 8; df++){
        const int d = df * 8 + jcol;
        float v0 = oacc[df][0] * inv0, v1 = oacc[df][1] * inv0;
        float v2 = oacc[df][2] * inv1, v3 = oacc[df][3] * inv1;
        __nv_bfloat16 h0 = __float2bfloat16(v0), h1 = __float2bfloat16(v1);
        __nv_bfloat16 h2 = __float2bfloat16(v2), h3 = __float2bfloat16(v3);
        *(__nv_bfloat162*)&Ohi[orow0 + d] = __nv_bfloat162(h0, h1);
        *(__nv_bfloat162*)&Ohi[orow1 + d] = __nv_bfloat162(h2, h3);
        *(__nv_bfloat162*)&Olo[orow0 + d] = __nv_bfloat162(
            __float2bfloat16(v0 - __bfloat162float(h0)),
            __float2bfloat16(v1 - __bfloat162float(h1)));
        *(__nv_bfloat162*)&Olo[orow1 + d] = __nv_bfloat162(
            __float2bfloat16(v2 - __bfloat162float(h2)),
            __float2bfloat16(v3 - __bfloat162float(h3)));
    }
}

// ---------------------------------------------------------------------------
extern "C" void kernel_launch(void* const* d_in, const int* in_sizes, int n_in,
                              void* d_out, int out_size)
{
    const float* query = (const float*)d_in[0];
    const float* key   = (const float*)d_in[1];
    const float* value = (const float*)d_in[2];
    const float* Wq    = (const float*)d_in[3];
    const float* bq    = (const float*)d_in[4];
    const float* Wk    = (const float*)d_in[5];
    const float* bk    = (const float*)d_in[6];
    const float* Wv    = (const float*)d_in[7];
    const float* bv    = (const float*)d_in[8];
    const float* Wo    = (const float*)d_in[9];
    const float* bo    = (const float*)d_in[10];
    float* out = (float*)d_out;

    __nv_bfloat16 *a3hi, *a3lo, *w3hi, *w3lo, *wohi, *wolo;
    __nv_bfloat16 *qkvhi, *qkvlo, *athi, *atlo;
    cudaGetSymbolAddress((void**)&a3hi,  g_a3hi);
    cudaGetSymbolAddress((void**)&a3lo,  g_a3lo);
    cudaGetSymbolAddress((void**)&w3hi,  g_w3hi);
    cudaGetSymbolAddress((void**)&w3lo,  g_w3lo);
    cudaGetSymbolAddress((void**)&wohi,  g_wohi);
    cudaGetSymbolAddress((void**)&wolo,  g_wolo);
    cudaGetSymbolAddress((void**)&qkvhi, g_qkvhi);
    cudaGetSymbolAddress((void**)&qkvlo, g_qkvlo);
    cudaGetSymbolAddress((void**)&athi,  g_athi);
    cudaGetSymbolAddress((void**)&atlo,  g_atlo);

    static int attr_set = 0;
    const int gemm_smem = NSTG * STB;        // 192 KB
    const int attn_smem = 2 * AT_STAGE;      // 64 KB
    if (!attr_set) {
        cudaFuncSetAttribute(gemm_mma_kernel,
                             cudaFuncAttributeMaxDynamicSharedMemorySize, gemm_smem);
        cudaFuncSetAttribute(attn_mma_kernel,
                             cudaFuncAttributeMaxDynamicSharedMemorySize, attn_smem);
        attr_set = 1;
    }

    // fused activation split (q|k|v) + fused weight transpose/split (4 weights)
    split3_kernel<<<3 * 8192, 256>>>(query, key, value,
                                     (__nv_bfloat162*)a3hi, (__nv_bfloat162*)a3lo);
    dim3 tgrid(Pp / 32, Dd / 32, 4);
    dim3 tblk(32, 8);
    tsplit4_kernel<<<tgrid, tblk>>>(Wq, Wk, Wv, Wo, w3hi, w3lo, wohi, wolo);

    // fused QKV projection: grid (24, 64)
    dim3 qkvgrid(3 * Pp / 128, Mm / 128);
    gemm_mma_kernel<<<qkvgrid, 256, gemm_smem>>>(
        a3hi, a3lo, w3hi, w3lo, bq, bk, bv,
        nullptr, qkvhi, qkvlo, 1);

    // attention: grid (16, 64), 256 threads, 128 q-rows per CTA
    const size_t seg = (size_t)Bb * Hh * Ss * KD;
    dim3 agrid(Ss / 128, Bb * Hh);
    attn_mma_kernel<<<agrid, 256, attn_smem>>>(
        qkvhi, qkvlo, qkvhi + seg, qkvlo + seg, qkvhi + 2*seg, qkvlo + 2*seg,
        athi, atlo);

    // output projection: grid (8, 64)
    dim3 ogrid(Pp / 128, Mm / 128);
    gemm_mma_kernel<<<ogrid, 256, gemm_smem>>>(
        athi, atlo, wohi, wolo, bo, bo, bo,
        out, nullptr, nullptr, 0);
}